// round 1
// baseline (speedup 1.0000x reference)
#include <cuda_runtime.h>

// Shapes (fixed by the problem config)
#define B_   8
#define C_   64
#define T_   50
#define H_   64
#define W_   64
#define HO_  32
#define WO_  32
#define HW_  (H_ * W_)     // 4096
#define OHW_ (HO_ * WO_)   // 1024
#define N_OUT ((long long)B_ * C_ * T_ * HO_ * WO_)  // 26,214,400

// One block per (b,c) plane. Thread tid = ho*32+wo owns one 2x2 pooling window.
// Phase 1: sequential cumsum-then-sum over t for the 4 window pixels
//          (matches reference fp32 recurrence: acc += x; tot += acc).
// Phase 2: first-max argmax over the 4 totals, then gather x at the winning
//          flat (h*W+w) index for every t. No inter-thread communication.
__global__ __launch_bounds__(1024, 1)
void spike_pool_fused(const float* __restrict__ x, float* __restrict__ out) {
    const int bc  = blockIdx.x;          // 0..511  (b*64 + c)
    const int tid = threadIdx.x;         // 0..1023
    const int ho  = tid >> 5;
    const int wo  = tid & 31;

    const float* xplane = x + (size_t)bc * T_ * HW_;
    const float* xp = xplane + (2 * ho) * W_ + 2 * wo;

    float a0 = 0.f, a1 = 0.f, a2 = 0.f, a3 = 0.f;   // running cumsum per pixel
    float s0 = 0.f, s1 = 0.f, s2 = 0.f, s3 = 0.f;   // sum of cumsums

    #pragma unroll 5
    for (int t = 0; t < T_; ++t) {
        const float2 r0 = *reinterpret_cast<const float2*>(xp + (size_t)t * HW_);
        const float2 r1 = *reinterpret_cast<const float2*>(xp + (size_t)t * HW_ + W_);
        a0 += r0.x; a1 += r0.y; a2 += r1.x; a3 += r1.y;
        s0 += a0;   s1 += a1;   s2 += a2;   s3 += a3;
    }

    // First-max argmax, window order (kh,kw) = (0,0),(0,1),(1,0),(1,1)
    int   k    = 0;
    float best = s0;
    if (s1 > best) { best = s1; k = 1; }
    if (s2 > best) { best = s2; k = 2; }
    if (s3 > best) { best = s3; k = 3; }
    const int idx = (2 * ho + (k >> 1)) * W_ + (2 * wo + (k & 1));

    // Phase 2: gather winning location at every timestep.
    // Writes are fully coalesced (wo contiguous); reads hit L2 (data just streamed).
    float* op = out + (size_t)bc * T_ * OHW_ + tid;
    #pragma unroll 5
    for (int t = 0; t < T_; ++t) {
        op[(size_t)t * OHW_] = xplane[(size_t)t * HW_ + idx];
    }
}

// Zero the tail of d_out (loss scalar and any padding) — d_out is poisoned.
__global__ void tail_zero(float* __restrict__ out, long long n0, long long n) {
    long long i = n0 + (long long)blockIdx.x * blockDim.x + threadIdx.x;
    if (i < n) out[i] = 0.0f;
}

extern "C" void kernel_launch(void* const* d_in, const int* in_sizes, int n_in,
                              void* d_out, int out_size) {
    const float* x = (const float*)d_in[0];
    float* out = (float*)d_out;

    spike_pool_fused<<<B_ * C_, 1024>>>(x, out);

    long long total = (long long)out_size;
    if (total > N_OUT) {
        long long tail = total - N_OUT;
        int threads = 256;
        int blocks = (int)((tail + threads - 1) / threads);
        tail_zero<<<blocks, threads>>>(out, N_OUT, total);
    }
}

// round 2
// speedup vs baseline: 1.0921x; 1.0921x over previous
#include <cuda_runtime.h>

// Shapes (fixed by the problem config)
#define B_   8
#define C_   64
#define T_   50
#define H_   64
#define W_   64
#define HO_  32
#define WO_  32
#define HW_  (H_ * W_)     // 4096 floats per (b,c,t) plane
#define OHW_ (HO_ * WO_)   // 1024
#define N_OUT ((long long)B_ * C_ * T_ * HO_ * WO_)  // 26,214,400

// Block covers 8 window-rows (16 h-rows) of one (b,c) plane across all T.
// Region = 16 x 64 x 50 floats = 51200 floats = 200KB staged in smem so the
// phase-2 gather never goes back to HBM (the R1 kernel re-read ~400MB there).
#define REG_FLOATS (16 * 64 * T_)         // 51200
#define SMEM_BYTES (REG_FLOATS * 4)       // 204800

__global__ __launch_bounds__(1024, 1)
void spike_pool_smem(const float* __restrict__ x, float* __restrict__ out) {
    const int bc = blockIdx.x >> 2;   // (b*64 + c)
    const int r  = blockIdx.x & 3;    // which quarter of the 32 window-rows
    const int tid = threadIdx.x;

    extern __shared__ float sh[];     // [t][h_local(16)][w(64)] linear
    __shared__ int sidx[256];         // winning local flat index per window

    // ---- Phase 0: stream region gmem -> smem, fully coalesced float2 ----
    // Region per t is 1024 contiguous floats at plane offset r*1024.
    const float2* gp = (const float2*)(x + (size_t)bc * (T_ * HW_) + (size_t)r * 1024);
    float2* shp = (float2*)sh;
    #pragma unroll
    for (int j = 0; j < 25; ++j) {
        const int l = j * 1024 + tid;   // 0..25599 over (t, within) float2s
        const int t = l >> 9;           // 512 float2 per region-plane
        const int w = l & 511;
        shp[l] = gp[(size_t)t * (HW_ / 2) + w];
    }
    __syncthreads();

    // ---- Phase 1: per-window cumsum-then-sum recurrence (identical FP order
    //      to the rel_err==0 R1 kernel), then first-max argmax ----
    if (tid < 256) {
        const int ho_l = tid >> 5;            // 0..7
        const int wo   = tid & 31;
        const int row0 = (2 * ho_l) * 64 + 2 * wo;   // local flat offset

        float a0 = 0.f, a1 = 0.f, a2 = 0.f, a3 = 0.f;
        float s0 = 0.f, s1 = 0.f, s2 = 0.f, s3 = 0.f;
        #pragma unroll 5
        for (int t = 0; t < T_; ++t) {
            const float* b = sh + t * 1024 + row0;
            const float2 r0 = *reinterpret_cast<const float2*>(b);
            const float2 r1 = *reinterpret_cast<const float2*>(b + 64);
            a0 += r0.x; a1 += r0.y; a2 += r1.x; a3 += r1.y;
            s0 += a0;   s1 += a1;   s2 += a2;   s3 += a3;
        }
        int   k    = 0;
        float best = s0;
        if (s1 > best) { best = s1; k = 1; }
        if (s2 > best) { best = s2; k = 2; }
        if (s3 > best) { best = s3; k = 3; }
        sidx[tid] = row0 + (k >> 1) * 64 + (k & 1);
    }
    __syncthreads();

    // ---- Phase 2: gather winner from smem for every t, coalesced writes ----
    const int g  = tid >> 8;      // t-group 0..3
    const int wl = tid & 255;     // window within block
    const int idx = sidx[wl];
    float* ob = out + (size_t)bc * (T_ * OHW_) + r * 256 + wl;
    for (int t = g; t < T_; t += 4) {
        ob[(size_t)t * OHW_] = sh[t * 1024 + idx];
    }
}

// Zero the tail of d_out (loss scalar / padding) — d_out is poisoned.
__global__ void tail_zero(float* __restrict__ out, long long n0, long long n) {
    long long i = n0 + (long long)blockIdx.x * blockDim.x + threadIdx.x;
    if (i < n) out[i] = 0.0f;
}

extern "C" void kernel_launch(void* const* d_in, const int* in_sizes, int n_in,
                              void* d_out, int out_size) {
    const float* x = (const float*)d_in[0];
    float* out = (float*)d_out;

    cudaFuncSetAttribute(spike_pool_smem,
                         cudaFuncAttributeMaxDynamicSharedMemorySize, SMEM_BYTES);

    spike_pool_smem<<<B_ * C_ * 4, 1024, SMEM_BYTES>>>(x, out);

    long long total = (long long)out_size;
    if (total > N_OUT) {
        long long tail = total - N_OUT;
        int threads = 256;
        int blocks = (int)((tail + threads - 1) / threads);
        tail_zero<<<blocks, threads>>>(out, N_OUT, total);
    }
}

// round 5
// speedup vs baseline: 1.2636x; 1.1570x over previous
#include <cuda_runtime.h>

// Shapes (fixed by the problem config)
#define B_   8
#define C_   64
#define T_   50
#define H_   64
#define W_   64
#define HO_  32
#define WO_  32
#define HW_  (H_ * W_)     // 4096 floats per (b,c,t) plane
#define OHW_ (HO_ * WO_)   // 1024
#define N_OUT ((long long)B_ * C_ * T_ * HO_ * WO_)  // 26,214,400

// Block covers 4 window-rows (8 h-rows) of one (b,c) plane across all T.
// Region = 8 x 64 x 50 floats = 100KB smem -> 2 blocks/SM so one block's
// gmem loads overlap the other's compute+write phases.
#define REG_FLOATS (8 * 64 * T_)          // 25600
#define REG_F4     (REG_FLOATS / 4)       // 6400 float4s
#define SMEM_BYTES (REG_FLOATS * 4)       // 102400
#define NWIN 128                          // windows per block
#define NTHREADS 512

__global__ __launch_bounds__(NTHREADS, 2)
void spike_pool_smem(const float* __restrict__ x, float* __restrict__ out) {
    const int bc = blockIdx.x >> 3;   // (b*64 + c)
    const int r  = blockIdx.x & 7;    // which eighth of the 32 window-rows
    const int tid = threadIdx.x;

    extern __shared__ float sh[];     // [t][h_local(8)][w(64)] linear
    __shared__ int sidx[NWIN];        // winning local flat index per window

    // ---- Phase 0: stream region gmem -> smem, coalesced float4 ----
    // Region per t is 512 contiguous floats at plane offset r*512.
    // 6400 float4s / 512 threads = 12.5 -> 13 iterations with a guard.
    const float4* gp = (const float4*)(x + (size_t)bc * (T_ * HW_) + (size_t)r * 512);
    float4* shp = (float4*)sh;
    #pragma unroll
    for (int j = 0; j < 13; ++j) {
        const int l = j * NTHREADS + tid;   // float4 index over (t, within)
        if (l < REG_F4) {
            const int t = l >> 7;           // 128 float4 per region-plane
            const int w = l & 127;
            shp[l] = gp[(size_t)t * (HW_ / 4) + w];
        }
    }
    __syncthreads();

    // ---- Phase 1: per-window cumsum-then-sum recurrence (identical FP order
    //      to the rel_err==0 kernels), then first-max argmax ----
    if (tid < NWIN) {
        const int ho_l = tid >> 5;            // 0..3
        const int wo   = tid & 31;
        const int row0 = (2 * ho_l) * 64 + 2 * wo;   // local flat offset

        float a0 = 0.f, a1 = 0.f, a2 = 0.f, a3 = 0.f;
        float s0 = 0.f, s1 = 0.f, s2 = 0.f, s3 = 0.f;
        #pragma unroll 5
        for (int t = 0; t < T_; ++t) {
            const float* b = sh + t * 512 + row0;
            const float2 r0 = *reinterpret_cast<const float2*>(b);
            const float2 r1 = *reinterpret_cast<const float2*>(b + 64);
            a0 += r0.x; a1 += r0.y; a2 += r1.x; a3 += r1.y;
            s0 += a0;   s1 += a1;   s2 += a2;   s3 += a3;
        }
        int   k    = 0;
        float best = s0;
        if (s1 > best) { best = s1; k = 1; }
        if (s2 > best) { best = s2; k = 2; }
        if (s3 > best) { best = s3; k = 3; }
        sidx[tid] = row0 + (k >> 1) * 64 + (k & 1);
    }
    __syncthreads();

    // ---- Phase 2: gather winner from smem for every t, coalesced writes ----
    const int g  = tid >> 7;      // t-group 0..3
    const int wl = tid & 127;     // window within block
    const int idx = sidx[wl];
    float* ob = out + (size_t)bc * (T_ * OHW_) + r * NWIN + wl;
    for (int t = g; t < T_; t += 4) {
        ob[(size_t)t * OHW_] = sh[t * 512 + idx];
    }
}

// Zero the tail of d_out (loss scalar / padding) — d_out is poisoned.
__global__ void tail_zero(float* __restrict__ out, long long n0, long long n) {
    long long i = n0 + (long long)blockIdx.x * blockDim.x + threadIdx.x;
    if (i < n) out[i] = 0.0f;
}

extern "C" void kernel_launch(void* const* d_in, const int* in_sizes, int n_in,
                              void* d_out, int out_size) {
    const float* x = (const float*)d_in[0];
    float* out = (float*)d_out;

    cudaFuncSetAttribute(spike_pool_smem,
                         cudaFuncAttributeMaxDynamicSharedMemorySize, SMEM_BYTES);

    spike_pool_smem<<<B_ * C_ * 8, NTHREADS, SMEM_BYTES>>>(x, out);

    long long total = (long long)out_size;
    if (total > N_OUT) {
        long long tail = total - N_OUT;
        int threads = 256;
        int blocks = (int)((tail + threads - 1) / threads);
        tail_zero<<<blocks, threads>>>(out, N_OUT, total);
    }
}

// round 6
// speedup vs baseline: 1.7643x; 1.3963x over previous
#include <cuda_runtime.h>
#include <cuda_pipeline_primitives.h>

// Shapes (fixed by the problem config)
#define B_   8
#define C_   64
#define T_   50
#define H_   64
#define W_   64
#define HO_  32
#define WO_  32
#define HW_  (H_ * W_)     // 4096 floats per (b,c,t) plane
#define OHW_ (HO_ * WO_)   // 1024
#define N_OUT ((long long)B_ * C_ * T_ * HO_ * WO_)  // 26,214,400

// Block covers 2 window-rows (4 h-rows) of one (b,c) plane across all T.
// Region = 4 x 64 x 50 floats = 50KB smem -> 4 blocks/SM for fine-grained
// overlap of load/compute/write phases across resident blocks.
#define REG_FLOATS (4 * 64 * T_)          // 12800
#define REG_F4     (REG_FLOATS / 4)       // 3200 float4s
#define SMEM_BYTES (REG_FLOATS * 4)       // 51200
#define NWIN 64                           // windows per block
#define NTHREADS 256

__global__ __launch_bounds__(NTHREADS, 4)
void spike_pool_smem(const float* __restrict__ x, float* __restrict__ out,
                     long long total_out) {
    const int bc = blockIdx.x >> 4;   // (b*64 + c)
    const int r  = blockIdx.x & 15;   // which sixteenth of the 32 window-rows
    const int tid = threadIdx.x;

    extern __shared__ float sh[];     // [t][h_local(4)][w(64)] linear
    __shared__ int sidx[NWIN];        // winning local flat index per window

    // ---- Phase 0: stream region gmem -> smem via cp.async (LDGSTS.128) ----
    // Region per t is 256 contiguous floats (64 float4) at plane offset r*256.
    const float4* gp = (const float4*)(x + (size_t)bc * (T_ * HW_) + (size_t)r * 256);
    float4* shp = (float4*)sh;
    #pragma unroll
    for (int j = 0; j < 13; ++j) {
        const int l = j * NTHREADS + tid;   // float4 index over (t, within)
        if (l < REG_F4) {
            const int t = l >> 6;           // 64 float4 per region-plane
            const int w = l & 63;
            __pipeline_memcpy_async(&shp[l], &gp[(size_t)t * (HW_ / 4) + w],
                                    sizeof(float4));
        }
    }
    __pipeline_commit();

    // Zero the out tail (loss scalar / padding) while loads are in flight.
    if (blockIdx.x == 0 && tid == 0) {
        for (long long i = N_OUT; i < total_out; ++i) out[i] = 0.0f;
    }

    __pipeline_wait_prior(0);
    __syncthreads();

    // ---- Phase 1: per-window cumsum-then-sum recurrence (identical FP order
    //      to the rel_err==0 kernels), then first-max argmax ----
    if (tid < NWIN) {
        const int ho_l = tid >> 5;            // 0..1
        const int wo   = tid & 31;
        const int row0 = (2 * ho_l) * 64 + 2 * wo;   // local flat offset

        float a0 = 0.f, a1 = 0.f, a2 = 0.f, a3 = 0.f;
        float s0 = 0.f, s1 = 0.f, s2 = 0.f, s3 = 0.f;
        #pragma unroll 5
        for (int t = 0; t < T_; ++t) {
            const float* b = sh + t * 256 + row0;
            const float2 r0 = *reinterpret_cast<const float2*>(b);
            const float2 r1 = *reinterpret_cast<const float2*>(b + 64);
            a0 += r0.x; a1 += r0.y; a2 += r1.x; a3 += r1.y;
            s0 += a0;   s1 += a1;   s2 += a2;   s3 += a3;
        }
        int   k    = 0;
        float best = s0;
        if (s1 > best) { best = s1; k = 1; }
        if (s2 > best) { best = s2; k = 2; }
        if (s3 > best) { best = s3; k = 3; }
        sidx[tid] = row0 + (k >> 1) * 64 + (k & 1);
    }
    __syncthreads();

    // ---- Phase 2: gather winner from smem for every t, coalesced writes ----
    const int g  = tid >> 6;      // t-group 0..3
    const int wl = tid & 63;      // window within block
    const int idx = sidx[wl];
    float* ob = out + (size_t)bc * (T_ * OHW_) + r * NWIN + wl;
    #pragma unroll
    for (int t = g; t < T_; t += 4) {
        ob[(size_t)t * OHW_] = sh[t * 256 + idx];
    }
}

extern "C" void kernel_launch(void* const* d_in, const int* in_sizes, int n_in,
                              void* d_out, int out_size) {
    const float* x = (const float*)d_in[0];
    float* out = (float*)d_out;

    cudaFuncSetAttribute(spike_pool_smem,
                         cudaFuncAttributeMaxDynamicSharedMemorySize, SMEM_BYTES);

    spike_pool_smem<<<B_ * C_ * 16, NTHREADS, SMEM_BYTES>>>(
        x, out, (long long)out_size);
}

// round 7
// speedup vs baseline: 1.7680x; 1.0021x over previous
#include <cuda_runtime.h>
#include <cuda_pipeline_primitives.h>

// Shapes (fixed by the problem config)
#define B_   8
#define C_   64
#define T_   50
#define H_   64
#define W_   64
#define HO_  32
#define WO_  32
#define HW_  (H_ * W_)     // 4096 floats per (b,c,t) plane
#define OHW_ (HO_ * WO_)   // 1024
#define N_OUT ((long long)B_ * C_ * T_ * HO_ * WO_)  // 26,214,400

// Block covers ONE window-row (2 h-rows) of one (b,c) plane across all T.
// Region = 2 x 64 x 50 floats = 25.6KB smem -> 8 blocks/SM for maximal
// phase decorrelation (load/compute/write overlap across resident blocks).
#define REG_FLOATS (2 * 64 * T_)          // 6400
#define REG_F4     (REG_FLOATS / 4)       // 1600 float4s
#define SMEM_BYTES (REG_FLOATS * 4)       // 25600
#define NWIN 32                           // windows per block
#define NTHREADS 128

__global__ __launch_bounds__(NTHREADS, 8)
void spike_pool_smem(const float* __restrict__ x, float* __restrict__ out,
                     long long total_out) {
    const int bc = blockIdx.x >> 5;   // (b*64 + c)
    const int r  = blockIdx.x & 31;   // which window-row of the 32
    const int tid = threadIdx.x;

    extern __shared__ float sh[];     // [t][h_local(2)][w(64)] linear, 128/t
    __shared__ int sidx[NWIN];        // winning local flat index per window

    // ---- Phase 0: stream region gmem -> smem via cp.async (LDGSTS.128) ----
    // Region per t is 128 contiguous floats (32 float4) at plane offset r*128.
    const float4* gp = (const float4*)(x + (size_t)bc * (T_ * HW_) + (size_t)r * 128);
    float4* shp = (float4*)sh;
    #pragma unroll
    for (int j = 0; j < 13; ++j) {
        const int l = j * NTHREADS + tid;   // float4 index over (t, within)
        if (l < REG_F4) {
            const int t = l >> 5;           // 32 float4 per region-plane
            const int w = l & 31;
            __pipeline_memcpy_async(&shp[l], &gp[(size_t)t * (HW_ / 4) + w],
                                    sizeof(float4));
        }
    }
    __pipeline_commit();

    // Zero the out tail (loss scalar / padding) while loads are in flight.
    if (blockIdx.x == 0 && tid == 0) {
        for (long long i = N_OUT; i < total_out; ++i) out[i] = 0.0f;
    }

    __pipeline_wait_prior(0);
    __syncthreads();

    // ---- Phase 1: one thread per (window, pixel). Each pixel's cumsum-then-
    //      sum recurrence is an independent chain with FP order identical to
    //      the rel_err==0 kernels. Combine 4 pixels via shfl, first-max rule.
    {
        const int w = tid >> 2;           // window 0..31
        const int p = tid & 3;            // pixel (kh*2+kw) 0..3
        const int off = 2 * w + (p >> 1) * 64 + (p & 1);

        float a = 0.f, s = 0.f;
        #pragma unroll 10
        for (int t = 0; t < T_; ++t) {
            a += sh[t * 128 + off];
            s += a;
        }

        const unsigned full = 0xFFFFFFFFu;
        const int base = (tid & 31) & ~3;     // lane of pixel 0 in this group
        const float s0 = __shfl_sync(full, s, base + 0);
        const float s1 = __shfl_sync(full, s, base + 1);
        const float s2 = __shfl_sync(full, s, base + 2);
        const float s3 = __shfl_sync(full, s, base + 3);

        int   k    = 0;
        float best = s0;
        if (s1 > best) { best = s1; k = 1; }
        if (s2 > best) { best = s2; k = 2; }
        if (s3 > best) { best = s3; k = 3; }
        if (p == 0) sidx[w] = 2 * w + (k >> 1) * 64 + (k & 1);
    }
    __syncthreads();

    // ---- Phase 2: gather winner from smem for every t, coalesced writes ----
    const int g  = tid >> 5;      // t-group 0..3
    const int wl = tid & 31;      // window within block
    const int idx = sidx[wl];
    float* ob = out + (size_t)bc * (T_ * OHW_) + r * NWIN + wl;
    #pragma unroll
    for (int t = g; t < T_; t += 4) {
        ob[(size_t)t * OHW_] = sh[t * 128 + idx];
    }
}

extern "C" void kernel_launch(void* const* d_in, const int* in_sizes, int n_in,
                              void* d_out, int out_size) {
    const float* x = (const float*)d_in[0];
    float* out = (float*)d_out;

    cudaFuncSetAttribute(spike_pool_smem,
                         cudaFuncAttributeMaxDynamicSharedMemorySize, SMEM_BYTES);

    spike_pool_smem<<<B_ * C_ * 32, NTHREADS, SMEM_BYTES>>>(
        x, out, (long long)out_size);
}